// round 16
// baseline (speedup 1.0000x reference)
#include <cuda_runtime.h>
#include <cstdint>

#define CRF_B 512
#define CRF_S 512
#define CRF_T 64

// Per-batch partial results + completion ticket (device scratch; no allocs).
__device__ float    g_dpart[CRF_B];
__device__ float    g_npart[CRF_B];
__device__ unsigned g_ticket;   // zero-init; last CTA resets it each run

typedef unsigned long long u64;

// ---- packed f32x2 helpers (sm_100+ PTX) ----
__device__ __forceinline__ u64 ffma2(u64 a, u64 b, u64 c) {
    u64 d;
    asm("fma.rn.f32x2 %0, %1, %2, %3;" : "=l"(d) : "l"(a), "l"(b), "l"(c));
    return d;
}
__device__ __forceinline__ u64 fadd2(u64 a, u64 b) {
    u64 d;
    asm("add.rn.f32x2 %0, %1, %2;" : "=l"(d) : "l"(a), "l"(b));
    return d;
}
__device__ __forceinline__ u64 pack2(float x, float y) {
    u64 d;
    asm("mov.b64 %0, {%1, %2};" : "=l"(d) : "f"(x), "f"(y));
    return d;
}
__device__ __forceinline__ float2 unpack2(u64 a) {
    float2 r;
    asm("mov.b64 {%0, %1}, %2;" : "=f"(r.x), "=f"(r.y) : "l"(a));
    return r;
}

// Warp-uniform layout detection (ballot => uniform, no global state).
__device__ __forceinline__ int detect_mshift(const void* mask, int l) {
    const unsigned* mw = (const unsigned*)mask;
    unsigned bad = ((mw[l] | mw[l + 32]) & 0xFFFFFF00u) ? 1u : 0u;
    return __ballot_sync(0xffffffffu, bad) ? 0 : 2;   // u8 : i32
}
__device__ __forceinline__ int detect_tshift(const void* tags, int l) {
    const unsigned* tw = (const unsigned*)tags;
    unsigned odd = tw[2 * l + 1] ? 1u : 0u;
    return __ballot_sync(0xffffffffu, odd) ? 0 : 1;   // i32 : i64
}

// ============================================================================
// R15: TWO independent batches per forward warp. 64 blocks x 160 threads.
//   Warps 0-3: forward for batches bA=8*blk+2w, bB=bA+1. E=exp(trans) lives
//     once in registers (shared by both chains). Per fused step the two
//     independent GEMVs are interleaved (32 LDS.128 + 128 FFMA2) so each
//     chain's exchange/ chain-tail stalls are filled by the other chain's
//     issue stream. ONE __syncwarp covers both smem exchanges.
//   Warp 4: numerator (gold-path) for the block's 8 batches.
//   Last CTA: deterministic final reduction.
// Per-batch layout as R13: lane l owns states j0=2l,2l+1; p packed {p0,p1}
// (1 STS.64 per batch); renorm every 4 steps from exponent of p[state0]
// (broadcast load, warp-uniform, no shfl). allm fast path drops mask work.
// ============================================================================
__global__ void __launch_bounds__(160, 1) crf_main(
    const float* __restrict__ logits,
    const void* __restrict__ tagsv,
    const void* __restrict__ maskv,
    const float* __restrict__ trans,
    const float* __restrict__ startT,
    const float* __restrict__ endT,
    float* __restrict__ out)
{
    __shared__ __align__(16) u64 psm[8][2][32];   // [batch slot][pingpong][lane]
    __shared__ float rbuf[256];
    __shared__ int   do_red;

    const int tid = threadIdx.x;
    const int w   = tid >> 5;
    const int l   = tid & 31;

    const int msh = detect_mshift(maskv, l);

    if (w == 4) {
        // ---------------- Numerator warp: 8 batches ----------------
        const int tsh = detect_tshift(tagsv, l);
        const int*           tg  = (const int*)tagsv;
        const unsigned char* mkp = (const unsigned char*)maskv;

        for (int q = 0; q < 8; q++) {
            const int    b  = blockIdx.x * 8 + q;
            const float* lg = logits + (size_t)b * (CRF_S * CRF_T);
            const size_t eb = (size_t)b * CRF_S;

            float acc = 0.0f;
            int   cnt = 0;
            for (int s = l; s < CRF_S; s += 32) {
                const int  t = tg[(eb + s) << tsh];
                const bool m = (mkp[(eb + s) << msh] != 0);
                if (m) {
                    cnt++;
                    if (s < CRF_S - 1) acc += lg[(size_t)s * CRF_T + t];
                    if (s >= 1)        acc += trans[tg[(eb + s - 1) << tsh] * CRF_T + t];
                }
            }
#pragma unroll
            for (int o = 16; o; o >>= 1) {
                acc += __shfl_xor_sync(0xffffffffu, acc, o);
                cnt += __shfl_xor_sync(0xffffffffu, cnt, o);
            }
            if (l == 0) {
                acc += startT[tg[eb << tsh]];
                const int lt = tg[(eb + cnt - 1) << tsh];
                acc += endT[lt];
                if (mkp[(eb + CRF_S - 1) << msh]) acc += lg[(size_t)(CRF_S - 1) * CRF_T + lt];
                g_npart[b] = acc;
            }
        }
    } else {
        // ---------------- Forward warp: two batches ----------------
        const int bA = blockIdx.x * 8 + 2 * w;
        const int bB = bA + 1;
        const int j0 = 2 * l;
        const int slA = 2 * w;
        const int slB = 2 * w + 1;

        // E pairs along i for this lane's two columns (shared by both chains).
        u64 EA[32], EB[32];
#pragma unroll
        for (int k = 0; k < 32; k++) {
            const float* r0 = trans + (size_t)(2 * k)     * CRF_T + j0;
            const float* r1 = trans + (size_t)(2 * k + 1) * CRF_T + j0;
            EA[k] = pack2(__expf(r0[0]), __expf(r1[0]));
            EB[k] = pack2(__expf(r0[1]), __expf(r1[1]));
        }

        const float*         lgA = logits + (size_t)bA * (CRF_S * CRF_T);
        const float*         lgB = logits + (size_t)bB * (CRF_S * CRF_T);
        const unsigned char* mkA = (const unsigned char*)maskv + (((size_t)bA * CRF_S) << msh);
        const unsigned char* mkB = (const unsigned char*)maskv + (((size_t)bB * CRF_S) << msh);

        // All-ones-mask detection for both batches.
        bool allm;
        {
            unsigned bad = 0u;
            for (int k = l; k < CRF_S; k += 32) {
                bad |= (mkA[(size_t)k << msh] == 0) ? 1u : 0u;
                bad |= (mkB[(size_t)k << msh] == 0) ? 1u : 0u;
            }
            allm = (__ballot_sync(0xffffffffu, bad) == 0u);
        }

        // ---- init both batches: alpha0 -> exp-domain ----
        float CA, p0A, p1A, CB, p0B, p1B;
        {
            float2 l0 = ((const float2*)lgA)[l];
            float a0 = startT[j0] + l0.x;
            float a1 = startT[j0 + 1] + l0.y;
            float mx = fmaxf(a0, a1);
#pragma unroll
            for (int o = 16; o; o >>= 1) mx = fmaxf(mx, __shfl_xor_sync(0xffffffffu, mx, o));
            CA = mx; p0A = __expf(a0 - mx); p1A = __expf(a1 - mx);
            psm[slA][0][l] = pack2(p0A, p1A);
        }
        {
            float2 l0 = ((const float2*)lgB)[l];
            float a0 = startT[j0] + l0.x;
            float a1 = startT[j0 + 1] + l0.y;
            float mx = fmaxf(a0, a1);
#pragma unroll
            for (int o = 16; o; o >>= 1) mx = fmaxf(mx, __shfl_xor_sync(0xffffffffu, mx, o));
            CB = mx; p0B = __expf(a0 - mx); p1B = __expf(a1 - mx);
            psm[slB][0][l] = pack2(p0B, p1B);
        }

        // ---- prologue FIFOs (depth 4) + current-step exp, both batches ----
        float2 f2A = ((const float2*)(lgA + 2 * CRF_T))[l];
        float2 f3A = ((const float2*)(lgA + 3 * CRF_T))[l];
        float2 f4A = ((const float2*)(lgA + 4 * CRF_T))[l];
        float2 f5A = ((const float2*)(lgA + 5 * CRF_T))[l];
        float2 f2B = ((const float2*)(lgB + 2 * CRF_T))[l];
        float2 f3B = ((const float2*)(lgB + 3 * CRF_T))[l];
        float2 f4B = ((const float2*)(lgB + 4 * CRF_T))[l];
        float2 f5B = ((const float2*)(lgB + 5 * CRF_T))[l];
        unsigned char m2A = mkA[(size_t)2 << msh], m3A = mkA[(size_t)3 << msh];
        unsigned char m4A = mkA[(size_t)4 << msh], m5A = mkA[(size_t)5 << msh];
        unsigned char m2B = mkB[(size_t)2 << msh], m3B = mkB[(size_t)3 << msh];
        unsigned char m4B = mkB[(size_t)4 << msh], m5B = mkB[(size_t)5 << msh];
        float2 f1A = ((const float2*)(lgA + CRF_T))[l];
        float2 f1B = ((const float2*)(lgB + CRF_T))[l];
        float e0A = __expf(f1A.x), e1A = __expf(f1A.y);
        float e0B = __expf(f1B.x), e1B = __expf(f1B.y);
        unsigned char cmA = mkA[(size_t)1 << msh];
        unsigned char cmB = mkB[(size_t)1 << msh];
        __syncwarp();

        // One fused step: advances BOTH batches. um literal at call sites.
        auto step = [&](int s, bool um, int ping) {
            const ulonglong2* qA = (const ulonglong2*)psm[slA][ping];
            const ulonglong2* qB = (const ulonglong2*)psm[slB][ping];
            u64* dA = psm[slA][ping ^ 1];
            u64* dB = psm[slB][ping ^ 1];

            // Interleaved dual GEMV: 32 LDS.128, 128 FFMA2, 16 depth-8 chains.
            u64 uA0 = 0ull, uA1 = 0ull, uA2 = 0ull, uA3 = 0ull;  // A, j0
            u64 vA0 = 0ull, vA1 = 0ull, vA2 = 0ull, vA3 = 0ull;  // A, j1
            u64 uB0 = 0ull, uB1 = 0ull, uB2 = 0ull, uB3 = 0ull;  // B, j0
            u64 vB0 = 0ull, vB1 = 0ull, vB2 = 0ull, vB3 = 0ull;  // B, j1
            u64 qfA = 0ull, qfB = 0ull;    // {p[0],p[1]} per batch (renorm)
#pragma unroll
            for (int m = 0; m < 16; m += 2) {
                ulonglong2 qa = qA[m];
                ulonglong2 qb = qB[m];
                ulonglong2 qa2 = qA[m + 1];
                ulonglong2 qb2 = qB[m + 1];
                if (m == 0) { qfA = qa.x; qfB = qb.x; }
                uA0 = ffma2(EA[2 * m],     qa.x,  uA0);
                vA0 = ffma2(EB[2 * m],     qa.x,  vA0);
                uB0 = ffma2(EA[2 * m],     qb.x,  uB0);
                vB0 = ffma2(EB[2 * m],     qb.x,  vB0);
                uA1 = ffma2(EA[2 * m + 1], qa.y,  uA1);
                vA1 = ffma2(EB[2 * m + 1], qa.y,  vA1);
                uB1 = ffma2(EA[2 * m + 1], qb.y,  uB1);
                vB1 = ffma2(EB[2 * m + 1], qb.y,  vB1);
                uA2 = ffma2(EA[2 * m + 2], qa2.x, uA2);
                vA2 = ffma2(EB[2 * m + 2], qa2.x, vA2);
                uB2 = ffma2(EA[2 * m + 2], qb2.x, uB2);
                vB2 = ffma2(EB[2 * m + 2], qb2.x, vB2);
                uA3 = ffma2(EA[2 * m + 3], qa2.y, uA3);
                vA3 = ffma2(EB[2 * m + 3], qa2.y, vA3);
                uB3 = ffma2(EA[2 * m + 3], qb2.y, uB3);
                vB3 = ffma2(EB[2 * m + 3], qb2.y, vB3);
            }

            // FIFO rotate + clamped prefetch, both batches.
            const float2 headA = f2A, headB = f2B;
            const unsigned char mhA = m2A, mhB = m2B;
            f2A = f3A; f3A = f4A; f4A = f5A;
            f2B = f3B; f3B = f4B; f4B = f5B;
            const int sp = (s + 5 < CRF_S) ? (s + 5) : (CRF_S - 1);
            f5A = ((const float2*)(lgA + (size_t)sp * CRF_T))[l];
            f5B = ((const float2*)(lgB + (size_t)sp * CRF_T))[l];
            if (um) {
                m2A = m3A; m3A = m4A; m4A = m5A; m5A = mkA[(size_t)sp << msh];
                m2B = m3B; m3B = m4B; m4B = m5B; m5B = mkB[(size_t)sp << msh];
            }
            const float ne0A = __expf(headA.x), ne1A = __expf(headA.y);
            const float ne0B = __expf(headB.x), ne1B = __expf(headB.y);

            float2 sA0 = unpack2(fadd2(fadd2(uA0, uA1), fadd2(uA2, uA3)));
            float2 sA1 = unpack2(fadd2(fadd2(vA0, vA1), fadd2(vA2, vA3)));
            float2 sB0 = unpack2(fadd2(fadd2(uB0, uB1), fadd2(uB2, uB3)));
            float2 sB1 = unpack2(fadd2(fadd2(vB0, vB1), fadd2(vB2, vB3)));
            const float pnA0 = (sA0.x + sA0.y) * e0A;
            const float pnA1 = (sA1.x + sA1.y) * e1A;
            const float pnB0 = (sB0.x + sB0.y) * e0B;
            const float pnB1 = (sB1.x + sB1.y) * e1B;
            if (um) {
                if (cmA) { p0A = pnA0; p1A = pnA1; }
                if (cmB) { p0B = pnB0; p1B = pnB1; }
            } else {
                p0A = pnA0; p1A = pnA1;
                p0B = pnB0; p1B = pnB1;
            }

            // Exact power-of-2 renorm every 4 steps (per batch, shfl-free:
            // exponent of p[state0] from the broadcast load, warp-uniform).
            if ((s & 3) == 0) {
                const int eA = (int)((qfA >> 23) & 255ull);
                const float scA2 = __int_as_float((254 - eA) << 23);
                p0A *= scA2; p1A *= scA2;
                CA += (float)(eA - 127) * 0.6931471805599453f;
                const int eB = (int)((qfB >> 23) & 255ull);
                const float scB2 = __int_as_float((254 - eB) << 23);
                p0B *= scB2; p1B *= scB2;
                CB += (float)(eB - 127) * 0.6931471805599453f;
            }

            dA[l] = pack2(p0A, p1A);
            dB[l] = pack2(p0B, p1B);
            e0A = ne0A; e1A = ne1A; e0B = ne0B; e1B = ne1B;
            if (um) { cmA = mhA; cmB = mhB; }
            __syncwarp();
        };

        // s = 1..510 in pairs (static ping-pong), tail s = 511.
        if (allm) {
            for (int s = 1; s < CRF_S - 1; s += 2) {
                step(s,     false, 0);
                step(s + 1, false, 1);
            }
            step(CRF_S - 1, false, 0);
        } else {
            for (int s = 1; s < CRF_S - 1; s += 2) {
                step(s,     true, 0);
                step(s + 1, true, 1);
            }
            step(CRF_S - 1, true, 0);
        }

        // denom per batch = C + log(sum_j p_j * exp(end_j))
        {
            const float ee0 = __expf(endT[j0]);
            const float ee1 = __expf(endT[j0 + 1]);
            float vA = p0A * ee0 + p1A * ee1;
            float vB = p0B * ee0 + p1B * ee1;
#pragma unroll
            for (int o = 16; o; o >>= 1) {
                vA += __shfl_xor_sync(0xffffffffu, vA, o);
                vB += __shfl_xor_sync(0xffffffffu, vB, o);
            }
            if (l == 0) {
                g_dpart[bA] = CA + logf(vA);
                g_dpart[bB] = CB + logf(vB);
            }
        }
    }

    // ---- last CTA performs the final deterministic reduction ----
    __syncthreads();
    if (tid == 0) {
        __threadfence();
        unsigned t = atomicAdd(&g_ticket, 1u);
        do_red = (t == gridDim.x - 1);
    }
    __syncthreads();
    if (do_red) {
        __threadfence();
        float a = 0.0f;
        for (int i = tid; i < CRF_B; i += 160)     // fixed order per thread
            a += g_npart[i] - g_dpart[i];
        rbuf[tid] = a;
        if (tid < 96) rbuf[160 + tid] = 0.0f;
        __syncthreads();
        for (int o = 128; o; o >>= 1) {
            if (tid < o) rbuf[tid] += rbuf[tid + o];
            __syncthreads();
        }
        if (tid == 0) { out[0] = rbuf[0]; g_ticket = 0u; }
    }
}

extern "C" void kernel_launch(void* const* d_in, const int* in_sizes, int n_in,
                              void* d_out, int out_size)
{
    const float* logits = (const float*)d_in[0];
    const void*  tags   = d_in[1];
    const void*  mask   = d_in[2];
    const float* trans  = (const float*)d_in[3];
    const float* startT = (const float*)d_in[4];
    const float* endT   = (const float*)d_in[5];
    float*       out    = (float*)d_out;

    crf_main<<<CRF_B / 8, 160>>>(logits, tags, mask, trans, startT, endT, out);
}

// round 17
// speedup vs baseline: 1.0112x; 1.0112x over previous
#include <cuda_runtime.h>
#include <cstdint>

#define CRF_B 512
#define CRF_S 512
#define CRF_T 64

// Per-batch partial results + completion ticket (device scratch; no allocs).
__device__ float    g_dpart[CRF_B];
__device__ float    g_npart[CRF_B];
__device__ unsigned g_ticket;   // zero-init; last CTA resets it each run

typedef unsigned long long u64;

// ---- packed f32x2 helpers (sm_100+ PTX) ----
__device__ __forceinline__ u64 ffma2(u64 a, u64 b, u64 c) {
    u64 d;
    asm("fma.rn.f32x2 %0, %1, %2, %3;" : "=l"(d) : "l"(a), "l"(b), "l"(c));
    return d;
}
__device__ __forceinline__ u64 fadd2(u64 a, u64 b) {
    u64 d;
    asm("add.rn.f32x2 %0, %1, %2;" : "=l"(d) : "l"(a), "l"(b));
    return d;
}
__device__ __forceinline__ u64 pack2(float x, float y) {
    u64 d;
    asm("mov.b64 %0, {%1, %2};" : "=l"(d) : "f"(x), "f"(y));
    return d;
}
__device__ __forceinline__ float2 unpack2(u64 a) {
    float2 r;
    asm("mov.b64 {%0, %1}, %2;" : "=f"(r.x), "=f"(r.y) : "l"(a));
    return r;
}

// Warp-uniform layout detection (ballot => uniform, no global state).
__device__ __forceinline__ int detect_mshift(const void* mask, int l) {
    const unsigned* mw = (const unsigned*)mask;
    unsigned bad = ((mw[l] | mw[l + 32]) & 0xFFFFFF00u) ? 1u : 0u;
    return __ballot_sync(0xffffffffu, bad) ? 0 : 2;   // u8 : i32
}
__device__ __forceinline__ int detect_tshift(const void* tags, int l) {
    const unsigned* tw = (const unsigned*)tags;
    unsigned odd = tw[2 * l + 1] ? 1u : 0u;
    return __ballot_sync(0xffffffffu, odd) ? 0 : 1;   // i32 : i64
}

// ============================================================================
// R17: two batches per forward warp, SEQUENTIAL halves (register-disciplined
// rework of R15, whose fully-interleaved body hit regs=239 and serialized its
// loads). 64 blocks x 160 threads.
//   Warps 0-3: forward for batches bA=8*blk+2w, bB=bA+1. E=exp(trans) once in
//     registers, shared by both chains. Per fused step: GEMV(A); store A;
//     GEMV(B); store B; ONE __syncwarp. Accumulators (4 u64, depth 16) are
//     reused across the halves so only one batch's chains are live at a time;
//     the scheduler overlaps B's independent loads with A's tails.
//   Warp 4: numerator (gold-path) for the block's 8 batches.
//   Last CTA: deterministic final reduction.
// Per-batch layout as R13: lane l owns states j0=2l,2l+1; p packed {p0,p1};
// shfl-free power-of-2 renorm every 4 steps from exponent of p[state0];
// allm fast path removes all mask work; FIFO depth 2 (prefetch s+3).
// ============================================================================
__global__ void __launch_bounds__(160, 1) crf_main(
    const float* __restrict__ logits,
    const void* __restrict__ tagsv,
    const void* __restrict__ maskv,
    const float* __restrict__ trans,
    const float* __restrict__ startT,
    const float* __restrict__ endT,
    float* __restrict__ out)
{
    __shared__ __align__(16) u64 psm[8][2][32];   // [batch slot][pingpong][lane]
    __shared__ float rbuf[256];
    __shared__ int   do_red;

    const int tid = threadIdx.x;
    const int w   = tid >> 5;
    const int l   = tid & 31;

    const int msh = detect_mshift(maskv, l);

    if (w == 4) {
        // ---------------- Numerator warp: 8 batches ----------------
        const int tsh = detect_tshift(tagsv, l);
        const int*           tg  = (const int*)tagsv;
        const unsigned char* mkp = (const unsigned char*)maskv;

        for (int q = 0; q < 8; q++) {
            const int    b  = blockIdx.x * 8 + q;
            const float* lg = logits + (size_t)b * (CRF_S * CRF_T);
            const size_t eb = (size_t)b * CRF_S;

            float acc = 0.0f;
            int   cnt = 0;
            for (int s = l; s < CRF_S; s += 32) {
                const int  t = tg[(eb + s) << tsh];
                const bool m = (mkp[(eb + s) << msh] != 0);
                if (m) {
                    cnt++;
                    if (s < CRF_S - 1) acc += lg[(size_t)s * CRF_T + t];
                    if (s >= 1)        acc += trans[tg[(eb + s - 1) << tsh] * CRF_T + t];
                }
            }
#pragma unroll
            for (int o = 16; o; o >>= 1) {
                acc += __shfl_xor_sync(0xffffffffu, acc, o);
                cnt += __shfl_xor_sync(0xffffffffu, cnt, o);
            }
            if (l == 0) {
                acc += startT[tg[eb << tsh]];
                const int lt = tg[(eb + cnt - 1) << tsh];
                acc += endT[lt];
                if (mkp[(eb + CRF_S - 1) << msh]) acc += lg[(size_t)(CRF_S - 1) * CRF_T + lt];
                g_npart[b] = acc;
            }
        }
    } else {
        // ---------------- Forward warp: two batches, sequential halves ------
        const int bA = blockIdx.x * 8 + 2 * w;
        const int bB = bA + 1;
        const int j0 = 2 * l;
        const int slA = 2 * w;
        const int slB = 2 * w + 1;

        // E pairs along i for this lane's two columns (shared by both chains).
        u64 EA[32], EB[32];
#pragma unroll
        for (int k = 0; k < 32; k++) {
            const float* r0 = trans + (size_t)(2 * k)     * CRF_T + j0;
            const float* r1 = trans + (size_t)(2 * k + 1) * CRF_T + j0;
            EA[k] = pack2(__expf(r0[0]), __expf(r1[0]));
            EB[k] = pack2(__expf(r0[1]), __expf(r1[1]));
        }

        const float*         lgA = logits + (size_t)bA * (CRF_S * CRF_T);
        const float*         lgB = logits + (size_t)bB * (CRF_S * CRF_T);
        const unsigned char* mkA = (const unsigned char*)maskv + (((size_t)bA * CRF_S) << msh);
        const unsigned char* mkB = (const unsigned char*)maskv + (((size_t)bB * CRF_S) << msh);

        // All-ones-mask detection for both batches.
        bool allm;
        {
            unsigned bad = 0u;
            for (int k = l; k < CRF_S; k += 32) {
                bad |= (mkA[(size_t)k << msh] == 0) ? 1u : 0u;
                bad |= (mkB[(size_t)k << msh] == 0) ? 1u : 0u;
            }
            allm = (__ballot_sync(0xffffffffu, bad) == 0u);
        }

        // ---- init both batches: alpha0 -> exp-domain ----
        float CA, p0A, p1A, CB, p0B, p1B;
        {
            float2 l0 = ((const float2*)lgA)[l];
            float a0 = startT[j0] + l0.x;
            float a1 = startT[j0 + 1] + l0.y;
            float mx = fmaxf(a0, a1);
#pragma unroll
            for (int o = 16; o; o >>= 1) mx = fmaxf(mx, __shfl_xor_sync(0xffffffffu, mx, o));
            CA = mx; p0A = __expf(a0 - mx); p1A = __expf(a1 - mx);
            psm[slA][0][l] = pack2(p0A, p1A);
        }
        {
            float2 l0 = ((const float2*)lgB)[l];
            float a0 = startT[j0] + l0.x;
            float a1 = startT[j0 + 1] + l0.y;
            float mx = fmaxf(a0, a1);
#pragma unroll
            for (int o = 16; o; o >>= 1) mx = fmaxf(mx, __shfl_xor_sync(0xffffffffu, mx, o));
            CB = mx; p0B = __expf(a0 - mx); p1B = __expf(a1 - mx);
            psm[slB][0][l] = pack2(p0B, p1B);
        }

        // ---- prologue: depth-2 FIFO per batch + current-step exp ----
        // Before step s: e = exp(row s), f2 = row s+1, f3 = row s+2.
        float2 f1A = ((const float2*)(lgA + CRF_T))[l];
        float2 f1B = ((const float2*)(lgB + CRF_T))[l];
        float2 f2A = ((const float2*)(lgA + 2 * CRF_T))[l];
        float2 f2B = ((const float2*)(lgB + 2 * CRF_T))[l];
        float2 f3A = ((const float2*)(lgA + 3 * CRF_T))[l];
        float2 f3B = ((const float2*)(lgB + 3 * CRF_T))[l];
        unsigned char m2A = mkA[(size_t)2 << msh], m3A = mkA[(size_t)3 << msh];
        unsigned char m2B = mkB[(size_t)2 << msh], m3B = mkB[(size_t)3 << msh];
        float e0A = __expf(f1A.x), e1A = __expf(f1A.y);
        float e0B = __expf(f1B.x), e1B = __expf(f1B.y);
        unsigned char cmA = mkA[(size_t)1 << msh];
        unsigned char cmB = mkB[(size_t)1 << msh];
        __syncwarp();

        // One fused step: batch A half then batch B half, one syncwarp.
        auto step = [&](int s, bool um, int ping) {
            const int sp = (s + 3 < CRF_S) ? (s + 3) : (CRF_S - 1);
            const bool renorm = ((s & 3) == 0);

            // ================= batch A =================
            {
                const ulonglong2* q2 = (const ulonglong2*)psm[slA][ping];
                u64 c0 = 0ull, c1 = 0ull, c2 = 0ull, c3 = 0ull;
                u64 qf = 0ull;
#pragma unroll
                for (int m = 0; m < 16; m += 2) {
                    ulonglong2 qa = q2[m];
                    ulonglong2 qb = q2[m + 1];
                    if (m == 0) qf = qa.x;
                    c0 = ffma2(EA[2 * m],     qa.x, c0);
                    c1 = ffma2(EB[2 * m],     qa.x, c1);
                    c0 = ffma2(EA[2 * m + 1], qa.y, c0);
                    c1 = ffma2(EB[2 * m + 1], qa.y, c1);
                    c2 = ffma2(EA[2 * m + 2], qb.x, c2);
                    c3 = ffma2(EB[2 * m + 2], qb.x, c3);
                    c2 = ffma2(EA[2 * m + 3], qb.y, c2);
                    c3 = ffma2(EB[2 * m + 3], qb.y, c3);
                }
                const float2 head      = f2A;
                const unsigned char mh = m2A;
                f2A = f3A;
                f3A = ((const float2*)(lgA + (size_t)sp * CRF_T))[l];
                if (um) { m2A = m3A; m3A = mkA[(size_t)sp << msh]; }
                const float ne0 = __expf(head.x);
                const float ne1 = __expf(head.y);

                float2 s0 = unpack2(fadd2(c0, c2));
                float2 s1 = unpack2(fadd2(c1, c3));
                const float pn0 = (s0.x + s0.y) * e0A;
                const float pn1 = (s1.x + s1.y) * e1A;
                if (um) {
                    if (cmA) { p0A = pn0; p1A = pn1; }
                } else {
                    p0A = pn0; p1A = pn1;
                }
                if (renorm) {
                    const int ex = (int)((qf >> 23) & 255ull);
                    const float sc = __int_as_float((254 - ex) << 23);
                    p0A *= sc; p1A *= sc;
                    CA += (float)(ex - 127) * 0.6931471805599453f;
                }
                psm[slA][ping ^ 1][l] = pack2(p0A, p1A);
                e0A = ne0; e1A = ne1;
                if (um) cmA = mh;
            }

            // ================= batch B =================
            {
                const ulonglong2* q2 = (const ulonglong2*)psm[slB][ping];
                u64 c0 = 0ull, c1 = 0ull, c2 = 0ull, c3 = 0ull;
                u64 qf = 0ull;
#pragma unroll
                for (int m = 0; m < 16; m += 2) {
                    ulonglong2 qa = q2[m];
                    ulonglong2 qb = q2[m + 1];
                    if (m == 0) qf = qa.x;
                    c0 = ffma2(EA[2 * m],     qa.x, c0);
                    c1 = ffma2(EB[2 * m],     qa.x, c1);
                    c0 = ffma2(EA[2 * m + 1], qa.y, c0);
                    c1 = ffma2(EB[2 * m + 1], qa.y, c1);
                    c2 = ffma2(EA[2 * m + 2], qb.x, c2);
                    c3 = ffma2(EB[2 * m + 2], qb.x, c3);
                    c2 = ffma2(EA[2 * m + 3], qb.y, c2);
                    c3 = ffma2(EB[2 * m + 3], qb.y, c3);
                }
                const float2 head      = f2B;
                const unsigned char mh = m2B;
                f2B = f3B;
                f3B = ((const float2*)(lgB + (size_t)sp * CRF_T))[l];
                if (um) { m2B = m3B; m3B = mkB[(size_t)sp << msh]; }
                const float ne0 = __expf(head.x);
                const float ne1 = __expf(head.y);

                float2 s0 = unpack2(fadd2(c0, c2));
                float2 s1 = unpack2(fadd2(c1, c3));
                const float pn0 = (s0.x + s0.y) * e0B;
                const float pn1 = (s1.x + s1.y) * e1B;
                if (um) {
                    if (cmB) { p0B = pn0; p1B = pn1; }
                } else {
                    p0B = pn0; p1B = pn1;
                }
                if (renorm) {
                    const int ex = (int)((qf >> 23) & 255ull);
                    const float sc = __int_as_float((254 - ex) << 23);
                    p0B *= sc; p1B *= sc;
                    CB += (float)(ex - 127) * 0.6931471805599453f;
                }
                psm[slB][ping ^ 1][l] = pack2(p0B, p1B);
                e0B = ne0; e1B = ne1;
                if (um) cmB = mh;
            }

            __syncwarp();
        };

        // s = 1..510 in pairs (static ping-pong), tail s = 511.
        if (allm) {
            for (int s = 1; s < CRF_S - 1; s += 2) {
                step(s,     false, 0);
                step(s + 1, false, 1);
            }
            step(CRF_S - 1, false, 0);
        } else {
            for (int s = 1; s < CRF_S - 1; s += 2) {
                step(s,     true, 0);
                step(s + 1, true, 1);
            }
            step(CRF_S - 1, true, 0);
        }

        // denom per batch = C + log(sum_j p_j * exp(end_j))
        {
            const float ee0 = __expf(endT[j0]);
            const float ee1 = __expf(endT[j0 + 1]);
            float vA = p0A * ee0 + p1A * ee1;
            float vB = p0B * ee0 + p1B * ee1;
#pragma unroll
            for (int o = 16; o; o >>= 1) {
                vA += __shfl_xor_sync(0xffffffffu, vA, o);
                vB += __shfl_xor_sync(0xffffffffu, vB, o);
            }
            if (l == 0) {
                g_dpart[bA] = CA + logf(vA);
                g_dpart[bB] = CB + logf(vB);
            }
        }
    }

    // ---- last CTA performs the final deterministic reduction ----
    __syncthreads();
    if (tid == 0) {
        __threadfence();
        unsigned t = atomicAdd(&g_ticket, 1u);
        do_red = (t == gridDim.x - 1);
    }
    __syncthreads();
    if (do_red) {
        __threadfence();
        float a = 0.0f;
        for (int i = tid; i < CRF_B; i += 160)     // fixed order per thread
            a += g_npart[i] - g_dpart[i];
        rbuf[tid] = a;
        if (tid < 96) rbuf[160 + tid] = 0.0f;
        __syncthreads();
        for (int o = 128; o; o >>= 1) {
            if (tid < o) rbuf[tid] += rbuf[tid + o];
            __syncthreads();
        }
        if (tid == 0) { out[0] = rbuf[0]; g_ticket = 0u; }
    }
}

extern "C" void kernel_launch(void* const* d_in, const int* in_sizes, int n_in,
                              void* d_out, int out_size)
{
    const float* logits = (const float*)d_in[0];
    const void*  tags   = d_in[1];
    const void*  mask   = d_in[2];
    const float* trans  = (const float*)d_in[3];
    const float* startT = (const float*)d_in[4];
    const float* endT   = (const float*)d_in[5];
    float*       out    = (float*)d_out;

    crf_main<<<CRF_B / 8, 160>>>(logits, tags, mask, trans, startT, endT, out);
}